// round 11
// baseline (speedup 1.0000x reference)
#include <cuda_runtime.h>

// Problem constants (from reference setup_inputs):
//   poses:       (4, 16, 16, 32, 4, 4)  float32
//   activations: (4, 16, 16, 32, 1, 1)  float32
//   pose_kernel: (3, 3, 32, 32, 4, 4)   float32
//   votes out:   (4, 14, 14, 3, 3, 32, 32, 4, 4)
//   act out:     (4, 14, 14, 3, 3, 32, 1, 1, 1)  appended after votes
// No contraction in the einsum -> votes is an elementwise broadcast product:
//   votes[b,h,w,x,y,i,o,m,n] = poses[b,h+x,w+y,i,m,n] * pk[x,y,i,o,m,n]
//
// FINAL (10-round session): bound by the HBM3e write-stream ceiling.
// 462MB of mandatory output writes per replay at ~6.0 TB/s achieved
// -> ~67-68us. This exact structure measured 5x at 67.1-68.1us
// (best 67.6us): one warp per tuple, ascending contiguous 512B-per-
// instruction write order, L1-cached reads, default write-back stores
// (output tail stays dirty in the 126MB L2), 85% occupancy.
// Falsified alternatives: combo-major mapping (77.9us), k-register-cache
// sweep (67.9us), TMA bulk stores (75.7us), 256-bit v8 ld/st (70.1us),
// ld.global.cg for pk (70.4us).

constexpr int B  = 4;
constexpr int H  = 16;
constexpr int W  = 16;
constexpr int OH = 14;
constexpr int OW = 14;
constexpr int KS = 3;
constexpr int IC = 32;
constexpr int OC = 32;
constexpr int AT = 16;   // 4x4 pose atom

constexpr int NPOS = B * OH * OW * KS * KS * IC;             // 225792 tuples
constexpr long long VOTES_ELEMS = (long long)NPOS * OC * AT; // 115,605,504
constexpr int THREADS = 256;
constexpr int BLOCKS  = NPOS * 32 / THREADS;                 // 28224 (exact)

// One warp per (b,h,w,ky,kx,i) tuple; the tuple's 512-float output block and
// matching pose_kernel block are both contiguous. Lane l, iter j handles
// float4 #(j*32+l): every LDG/STG.128 is a fully contiguous 512B warp
// transaction. Pose operand is atom float4 #(l&3) -> 4-way broadcast,
// L1-resident. Lane 0 writes the tuple's act_out element (fused).
__global__ __launch_bounds__(THREADS) void fused_kernel(
    const float* __restrict__ poses,
    const float* __restrict__ act,
    const float* __restrict__ pk,
    float* __restrict__ votes_out,
    float* __restrict__ act_out)
{
    int gwarp = (blockIdx.x * THREADS + threadIdx.x) >> 5;   // grid is exact
    int lane  = threadIdx.x & 31;

    int t = gwarp;
    int i = t & 31;  t >>= 5;     // in-capsule
    int y = t % KS;  t /= KS;     // kx
    int x = t % KS;  t /= KS;     // ky
    int w = t % OW;  t /= OW;
    int h = t % OH;  t /= OH;
    int b = t;

    int src_pix = ((b * H + (h + x)) * W + (w + y)) * IC + i;

    // pose atom: this lane always uses atom float4 #(lane & 3)
    float4 p = reinterpret_cast<const float4*>(poses)[src_pix * 4 + (lane & 3)];

    // kernel block for (x,y,i): 128 contiguous float4s
    const float4* kv = reinterpret_cast<const float4*>(pk)
                     + (long long)((x * KS + y) * IC + i) * (OC * AT / 4);
    // output block: 128 contiguous float4s
    float4* ov = reinterpret_cast<float4*>(votes_out)
               + (long long)gwarp * (OC * AT / 4);

#pragma unroll
    for (int j = 0; j < 4; ++j) {
        float4 k = kv[j * 32 + lane];
        float4 o;
        o.x = p.x * k.x;
        o.y = p.y * k.y;
        o.z = p.z * k.z;
        o.w = p.w * k.w;
        ov[j * 32 + lane] = o;
    }

    if (lane == 0) {
        act_out[gwarp] = act[src_pix];
    }
}

extern "C" void kernel_launch(void* const* d_in, const int* in_sizes, int n_in,
                              void* d_out, int out_size)
{
    const float* poses = (const float*)d_in[0];
    const float* acts  = (const float*)d_in[1];
    const float* pk    = (const float*)d_in[2];
    float* out = (float*)d_out;

    fused_kernel<<<BLOCKS, THREADS>>>(poses, acts, pk, out, out + VOTES_ELEMS);
}

// round 12
// speedup vs baseline: 1.0271x; 1.0271x over previous
#include <cuda_runtime.h>

// Problem constants (from reference setup_inputs):
//   poses:       (4, 16, 16, 32, 4, 4)  float32
//   activations: (4, 16, 16, 32, 1, 1)  float32
//   pose_kernel: (3, 3, 32, 32, 4, 4)   float32
//   votes out:   (4, 14, 14, 3, 3, 32, 32, 4, 4)
//   act out:     (4, 14, 14, 3, 3, 32, 1, 1, 1)  appended after votes
// No contraction in the einsum -> votes is an elementwise broadcast product:
//   votes[b,h,w,x,y,i,o,m,n] = poses[b,h+x,w+y,i,m,n] * pk[x,y,i,o,m,n]
//
// Session state: bound by the HBM3e write-stream ceiling (~6.0 TB/s,
// 462MB mandatory writes/replay -> ~67-68us). Winning structure measured
// 6x at 67.1-68.1us. This round: the ONE untested isolated lever --
// __stcs (evict-first) on votes stores atop the otherwise-unchanged winner.
// In steady-state graph replay the L2 dirty-tail benefit of write-back is
// zero-sum across replays; evict-first may let LTS drain writes earlier
// and smoother. Identical bytes, instructions, and mapping otherwise.

constexpr int B  = 4;
constexpr int H  = 16;
constexpr int W  = 16;
constexpr int OH = 14;
constexpr int OW = 14;
constexpr int KS = 3;
constexpr int IC = 32;
constexpr int OC = 32;
constexpr int AT = 16;   // 4x4 pose atom

constexpr int NPOS = B * OH * OW * KS * KS * IC;             // 225792 tuples
constexpr long long VOTES_ELEMS = (long long)NPOS * OC * AT; // 115,605,504
constexpr int THREADS = 256;
constexpr int BLOCKS  = NPOS * 32 / THREADS;                 // 28224 (exact)

// One warp per (b,h,w,ky,kx,i) tuple; the tuple's 512-float output block and
// matching pose_kernel block are both contiguous. Lane l, iter j handles
// float4 #(j*32+l): every LDG/STG.128 is a fully contiguous 512B warp
// transaction. Pose operand is atom float4 #(l&3) -> 4-way broadcast,
// L1-resident. Lane 0 writes the tuple's act_out element (fused).
__global__ __launch_bounds__(THREADS) void fused_kernel(
    const float* __restrict__ poses,
    const float* __restrict__ act,
    const float* __restrict__ pk,
    float* __restrict__ votes_out,
    float* __restrict__ act_out)
{
    int gwarp = (blockIdx.x * THREADS + threadIdx.x) >> 5;   // grid is exact
    int lane  = threadIdx.x & 31;

    int t = gwarp;
    int i = t & 31;  t >>= 5;     // in-capsule
    int y = t % KS;  t /= KS;     // kx
    int x = t % KS;  t /= KS;     // ky
    int w = t % OW;  t /= OW;
    int h = t % OH;  t /= OH;
    int b = t;

    int src_pix = ((b * H + (h + x)) * W + (w + y)) * IC + i;

    // pose atom: this lane always uses atom float4 #(lane & 3)
    float4 p = reinterpret_cast<const float4*>(poses)[src_pix * 4 + (lane & 3)];

    // kernel block for (x,y,i): 128 contiguous float4s
    const float4* kv = reinterpret_cast<const float4*>(pk)
                     + (long long)((x * KS + y) * IC + i) * (OC * AT / 4);
    // output block: 128 contiguous float4s
    float4* ov = reinterpret_cast<float4*>(votes_out)
               + (long long)gwarp * (OC * AT / 4);

#pragma unroll
    for (int j = 0; j < 4; ++j) {
        float4 k = kv[j * 32 + lane];
        float4 o;
        o.x = p.x * k.x;
        o.y = p.y * k.y;
        o.z = p.z * k.z;
        o.w = p.w * k.w;
        __stcs(&ov[j * 32 + lane], o);   // evict-first: sole diff vs winner
    }

    if (lane == 0) {
        act_out[gwarp] = act[src_pix];
    }
}

extern "C" void kernel_launch(void* const* d_in, const int* in_sizes, int n_in,
                              void* d_out, int out_size)
{
    const float* poses = (const float*)d_in[0];
    const float* acts  = (const float*)d_in[1];
    const float* pk    = (const float*)d_in[2];
    float* out = (float*)d_out;

    fused_kernel<<<BLOCKS, THREADS>>>(poses, acts, pk, out, out + VOTES_ELEMS);
}

// round 13
// speedup vs baseline: 1.0335x; 1.0063x over previous
#include <cuda_runtime.h>

// Problem constants (from reference setup_inputs):
//   poses:       (4, 16, 16, 32, 4, 4)  float32
//   activations: (4, 16, 16, 32, 1, 1)  float32
//   pose_kernel: (3, 3, 32, 32, 4, 4)   float32
//   votes out:   (4, 14, 14, 3, 3, 32, 32, 4, 4)
//   act out:     (4, 14, 14, 3, 3, 32, 1, 1, 1)  appended after votes
// No contraction in the einsum -> votes is an elementwise broadcast product:
//   votes[b,h,w,x,y,i,o,m,n] = poses[b,h+x,w+y,i,m,n] * pk[x,y,i,o,m,n]
//
// FINAL: bound by the HBM3e write-stream ceiling (~6.0 TB/s, 462MB
// mandatory writes/replay). Winning structure: one warp per tuple,
// ascending contiguous 512B-per-instruction write order, L1-cached reads,
// __stcs (evict-first) votes stores, 85% occupancy. Write-back variant
// measured 6x at 67.1-68.1us; __stcs variant measured 66.2us (R12) --
// this is its replication run. Falsified alternatives: combo-major mapping
// (77.9us), k-register-cache sweep (67.9us), TMA bulk stores (75.7us),
// 256-bit v8 ld/st (70.1us), ld.global.cg for pk (70.4us).

constexpr int B  = 4;
constexpr int H  = 16;
constexpr int W  = 16;
constexpr int OH = 14;
constexpr int OW = 14;
constexpr int KS = 3;
constexpr int IC = 32;
constexpr int OC = 32;
constexpr int AT = 16;   // 4x4 pose atom

constexpr int NPOS = B * OH * OW * KS * KS * IC;             // 225792 tuples
constexpr long long VOTES_ELEMS = (long long)NPOS * OC * AT; // 115,605,504
constexpr int THREADS = 256;
constexpr int BLOCKS  = NPOS * 32 / THREADS;                 // 28224 (exact)

// One warp per (b,h,w,ky,kx,i) tuple; the tuple's 512-float output block and
// matching pose_kernel block are both contiguous. Lane l, iter j handles
// float4 #(j*32+l): every LDG/STG.128 is a fully contiguous 512B warp
// transaction. Pose operand is atom float4 #(l&3) -> 4-way broadcast,
// L1-resident. Lane 0 writes the tuple's act_out element (fused).
__global__ __launch_bounds__(THREADS) void fused_kernel(
    const float* __restrict__ poses,
    const float* __restrict__ act,
    const float* __restrict__ pk,
    float* __restrict__ votes_out,
    float* __restrict__ act_out)
{
    int gwarp = (blockIdx.x * THREADS + threadIdx.x) >> 5;   // grid is exact
    int lane  = threadIdx.x & 31;

    int t = gwarp;
    int i = t & 31;  t >>= 5;     // in-capsule
    int y = t % KS;  t /= KS;     // kx
    int x = t % KS;  t /= KS;     // ky
    int w = t % OW;  t /= OW;
    int h = t % OH;  t /= OH;
    int b = t;

    int src_pix = ((b * H + (h + x)) * W + (w + y)) * IC + i;

    // pose atom: this lane always uses atom float4 #(lane & 3)
    float4 p = reinterpret_cast<const float4*>(poses)[src_pix * 4 + (lane & 3)];

    // kernel block for (x,y,i): 128 contiguous float4s
    const float4* kv = reinterpret_cast<const float4*>(pk)
                     + (long long)((x * KS + y) * IC + i) * (OC * AT / 4);
    // output block: 128 contiguous float4s
    float4* ov = reinterpret_cast<float4*>(votes_out)
               + (long long)gwarp * (OC * AT / 4);

#pragma unroll
    for (int j = 0; j < 4; ++j) {
        float4 k = kv[j * 32 + lane];
        float4 o;
        o.x = p.x * k.x;
        o.y = p.y * k.y;
        o.z = p.z * k.z;
        o.w = p.w * k.w;
        __stcs(&ov[j * 32 + lane], o);   // evict-first stores
    }

    if (lane == 0) {
        act_out[gwarp] = act[src_pix];
    }
}

extern "C" void kernel_launch(void* const* d_in, const int* in_sizes, int n_in,
                              void* d_out, int out_size)
{
    const float* poses = (const float*)d_in[0];
    const float* acts  = (const float*)d_in[1];
    const float* pk    = (const float*)d_in[2];
    float* out = (float*)d_out;

    fused_kernel<<<BLOCKS, THREADS>>>(poses, acts, pk, out, out + VOTES_ELEMS);
}